// round 16
// baseline (speedup 1.0000x reference)
#include <cuda_runtime.h>
#include <cuda_fp16.h>
#include <cstdint>

#define EMB 1024
#define NH  16
#define HD  64
#define BB  2
#define SS  2048
#define MT  4096

// ---------------------------------------------------------------------------
// Device global scratch (allocation-free rule)
// ---------------------------------------------------------------------------
__device__ __half g_iqh[MT*EMB], g_iql[MT*EMB];
__device__ __half g_ikh[MT*EMB], g_ikl[MT*EMB];
__device__ __half g_ivh[MT*EMB];
__device__ __half g_wqh[EMB*EMB], g_wql[EMB*EMB];
__device__ __half g_wkh[EMB*EMB], g_wkl[EMB*EMB];
__device__ __half g_wvh[EMB*EMB];
__device__ __half g_woh[EMB*EMB];
__device__ __half g_Qh[MT*EMB], g_Ql[MT*EMB];     // [B,H,S,D]
__device__ __half g_Kh[MT*EMB], g_Kl[MT*EMB];     // [B,H,S,D]
__device__ __half g_Vt[MT*EMB];                   // [B,H,D,S]
__device__ __half g_cth[MT*EMB];                  // [M,E] (hi only)

// work-stealing counters (zeroed in prep_split each launch)
__device__ int g_ctrP;
__device__ int g_ctrF;

#define P_TILES 768    // 32 x 8 x 3
#define F_TILES 512    // 16 x 32

// ---------------------------------------------------------------------------
// PTX helpers
// ---------------------------------------------------------------------------
__device__ __forceinline__ uint32_t smem_u32(const void* p) {
    uint32_t a;
    asm("{ .reg .u64 t; cvta.to.shared.u64 t, %1; cvt.u32.u64 %0, t; }" : "=r"(a) : "l"(p));
    return a;
}
__device__ __forceinline__ void cp16(uint32_t dst, const void* src) {
    asm volatile("cp.async.cg.shared.global [%0], [%1], 16;" :: "r"(dst), "l"(src));
}
#define CP_COMMIT() asm volatile("cp.async.commit_group;" ::: "memory")
#define CP_WAIT0()  asm volatile("cp.async.wait_group 0;" ::: "memory")

__device__ __forceinline__ void ldmx4(uint32_t* r, uint32_t a) {
    asm volatile("ldmatrix.sync.aligned.m8n8.x4.shared.b16 {%0,%1,%2,%3}, [%4];"
                 : "=r"(r[0]), "=r"(r[1]), "=r"(r[2]), "=r"(r[3]) : "r"(a));
}
__device__ __forceinline__ void mma_f16(float* d, const uint32_t* a, uint32_t b0, uint32_t b1) {
    asm volatile(
        "mma.sync.aligned.m16n8k16.row.col.f32.f16.f16.f32 "
        "{%0,%1,%2,%3},{%4,%5,%6,%7},{%8,%9},{%0,%1,%2,%3};"
        : "+f"(d[0]), "+f"(d[1]), "+f"(d[2]), "+f"(d[3])
        : "r"(a[0]), "r"(a[1]), "r"(a[2]), "r"(a[3]), "r"(b0), "r"(b1));
}
__device__ __forceinline__ float fexp2(float x) {
    float y;
    asm("ex2.approx.f32 %0, %1;" : "=f"(y) : "f"(x));
    return y;
}
__device__ __forceinline__ uint32_t h2u(__half2 h) { return *reinterpret_cast<uint32_t*>(&h); }
__device__ __forceinline__ void split2(float x, float y, uint32_t& hi, uint32_t& lo) {
    __half hx = __float2half_rn(x), hy = __float2half_rn(y);
    hi = h2u(__halves2half2(hx, hy));
    __half lx = __float2half_rn(x - __half2float(hx));
    __half ly = __float2half_rn(y - __half2float(hy));
    lo = h2u(__halves2half2(lx, ly));
}

// ---------------------------------------------------------------------------
// Prep: split q,k into fp16 hi/lo; v hi only; zero steal counters
// ---------------------------------------------------------------------------
__device__ __forceinline__ void split_store4(float4 a, __half* hp, __half* lp, int i4) {
    uint32_t h0, l0, h1, l1;
    split2(a.x, a.y, h0, l0);
    split2(a.z, a.w, h1, l1);
    uint2 uh; uh.x = h0; uh.y = h1;
    uint2 ul; ul.x = l0; ul.y = l1;
    ((uint2*)hp)[i4] = uh;
    ((uint2*)lp)[i4] = ul;
}
__global__ void prep_split(const float* __restrict__ q, const float* __restrict__ k,
                           const float* __restrict__ v)
{
    if (blockIdx.x == 0 && threadIdx.x == 0) { g_ctrP = 0; g_ctrF = 0; }
    int i4 = blockIdx.x * 256 + threadIdx.x;
    split_store4(((const float4*)q)[i4], g_iqh, g_iql, i4);
    split_store4(((const float4*)k)[i4], g_ikh, g_ikl, i4);
    float4 a = ((const float4*)v)[i4];
    uint2 uh;
    uh.x = h2u(__floats2half2_rn(a.x, a.y));
    uh.y = h2u(__floats2half2_rn(a.z, a.w));
    ((uint2*)g_ivh)[i4] = uh;
}

// ---------------------------------------------------------------------------
// Prep: transpose weights to [N=1024][K=1024] K-major.
// Wq,Wk: fp16 hi/lo split.  Wv,Wo: hi only.
// ---------------------------------------------------------------------------
__global__ void prep_w(const float* __restrict__ Wq, const float* __restrict__ Wk,
                       const float* __restrict__ Wv, const float* __restrict__ Wo)
{
    __shared__ float tile[32][33];
    const int z = blockIdx.z;
    const float* src = (z == 0) ? Wq : (z == 1) ? Wk : (z == 2) ? Wv : Wo;
    const int k0 = blockIdx.x * 32, n0 = blockIdx.y * 32;
    const int tx = threadIdx.x, ty = threadIdx.y;

    for (int r = ty; r < 32; r += 8) {
        int k = k0 + r, n = n0 + tx;
        tile[r][tx] = (z < 3) ? src[((size_t)(n >> 6) * EMB + k) * HD + (n & 63)]
                              : src[(size_t)k * EMB + n];
    }
    __syncthreads();
    for (int r = ty; r < 32; r += 8) {
        int n = n0 + r, k = k0 + tx;
        float vv = tile[tx][r];
        size_t o = (size_t)n * EMB + k;
        __half h = __float2half_rn(vv);
        if (z == 0) {
            g_wqh[o] = h;
            g_wql[o] = __float2half_rn(vv - __half2float(h));
        } else if (z == 1) {
            g_wkh[o] = h;
            g_wkl[o] = __float2half_rn(vv - __half2float(h));
        } else if (z == 2) {
            g_wvh[o] = h;
        } else {
            g_woh[o] = h;
        }
    }
}

// ---------------------------------------------------------------------------
// fp16 GEMM body, CTA 128x128, BK=32, 8 warps (4m x 2n), 2 CTAs/SM.
// Single-barrier software pipeline: [wait0; sync; issue next; compute].
// PASSES=3: AhBh+AhBl+AlBh.  PASSES=1: AhBh only.
// MODE 0: scatter hi/lo [B,H,S,D].  MODE 1: smem-transposed fp16 [B,H,D,S].
// MODE 2: fp32 linear [M,1024].
// ---------------------------------------------------------------------------
#define GSTAGE 40960   // Ah(10240) + Al + Bh + Bl slots

template<int PASSES>
__device__ __forceinline__ void gemm_load(uint32_t base,
    const __half* Ah, const __half* Al, const __half* Bh, const __half* Bl,
    int m0, int n0, int k0, int t)
{
#pragma unroll
    for (int rep = 0; rep < 2; rep++) {
        int c = t + rep * 256, r = c >> 2, cc = c & 3;
        size_t ao = (size_t)(m0 + r) * EMB + k0 + cc * 8;
        size_t bo = (size_t)(n0 + r) * EMB + k0 + cc * 8;
        uint32_t d = base + r * 80 + cc * 16;
        cp16(d, Ah + ao);
        if (PASSES == 3) cp16(d + 10240, Al + ao);
        cp16(d + 20480, Bh + bo);
        if (PASSES == 3) cp16(d + 30720, Bl + bo);
    }
    CP_COMMIT();
}

template<int MODE, int PASSES>
__device__ __forceinline__ void gemm_body(char* sm,
    const __half* Ah, const __half* Al,
    const __half* Bh, const __half* Bl,
    const float* bias, void* out0, void* out1, int bx, int by)
{
    const uint32_t sb = smem_u32(sm);
    const int t = threadIdx.x, wid = t >> 5, l = t & 31;
    const int g = l >> 2, tq = l & 3;
    const int m0 = bx * 128, n0 = by * 128;
    const int wm = wid & 3, wn = wid >> 2;

    float acc[2][8][4];
#pragma unroll
    for (int mt = 0; mt < 2; mt++)
#pragma unroll
        for (int nt = 0; nt < 8; nt++)
#pragma unroll
            for (int c = 0; c < 4; c++) acc[mt][nt][c] = 0.f;

    gemm_load<PASSES>(sb, Ah, Al, Bh, Bl, m0, n0, 0, t);

    for (int i = 0; i < 32; i++) {
        CP_WAIT0();
        __syncthreads();                 // publishes stage i; fences reads of slot (i+1)&1
        if (i + 1 < 32)
            gemm_load<PASSES>(sb + ((i + 1) & 1) * GSTAGE, Ah, Al, Bh, Bl, m0, n0, (i + 1) * 32, t);
        const uint32_t base = sb + (i & 1) * GSTAGE;

#pragma unroll
        for (int kt = 0; kt < 2; kt++) {
            uint32_t afh[2][4], afl[2][4];
#pragma unroll
            for (int mt = 0; mt < 2; mt++) {
                uint32_t off = (uint32_t)((wm * 32 + mt * 16 + (l & 15)) * 80
                                          + (kt * 16 + ((l >> 4) << 3)) * 2);
                ldmx4(afh[mt], base + off);
                if (PASSES == 3) ldmx4(afl[mt], base + 10240 + off);
            }
#pragma unroll
            for (int p = 0; p < 4; p++) {
                uint32_t off = (uint32_t)((wn * 64 + p * 16 + (l & 7) + (((l >> 4) & 1) << 3)) * 80
                                          + (kt * 16 + ((l >> 3) & 1) * 8) * 2);
                uint32_t rb[4];
                ldmx4(rb, base + 20480 + off);          // Bh frag
#pragma unroll
                for (int mt = 0; mt < 2; mt++) {
                    mma_f16(acc[mt][2 * p],     afh[mt], rb[0], rb[1]);
                    mma_f16(acc[mt][2 * p + 1], afh[mt], rb[2], rb[3]);
                    if (PASSES == 3) {
                        mma_f16(acc[mt][2 * p],     afl[mt], rb[0], rb[1]);
                        mma_f16(acc[mt][2 * p + 1], afl[mt], rb[2], rb[3]);
                    }
                }
                if (PASSES == 3) {
                    ldmx4(rb, base + 30720 + off);      // Bl frag
#pragma unroll
                    for (int mt = 0; mt < 2; mt++) {
                        mma_f16(acc[mt][2 * p],     afh[mt], rb[0], rb[1]);
                        mma_f16(acc[mt][2 * p + 1], afh[mt], rb[2], rb[3]);
                    }
                }
            }
        }
    }
    __syncthreads();                     // all compute done before any smem reuse

    if (MODE == 1) {
        // smem-staged transpose: T[128 n][136 pad] halves, then coalesced
        // 16B stores along S into g_Vt [B,H,D,S].
        __half* T = (__half*)sm;
        const int TP = 136;
#pragma unroll
        for (int mt = 0; mt < 2; mt++) {
            const int mlocA = wm * 32 + mt * 16 + g;
            const int mlocB = mlocA + 8;
#pragma unroll
            for (int nt = 0; nt < 8; nt++) {
                const int nloc = wn * 64 + nt * 8 + 2 * tq;
                const int n = n0 + nloc;
                const float b0 = bias[n], b1 = bias[n + 1];
                T[nloc * TP + mlocA]       = __float2half_rn(acc[mt][nt][0] + b0);
                T[(nloc + 1) * TP + mlocA] = __float2half_rn(acc[mt][nt][1] + b1);
                T[nloc * TP + mlocB]       = __float2half_rn(acc[mt][nt][2] + b0);
                T[(nloc + 1) * TP + mlocB] = __float2half_rn(acc[mt][nt][3] + b1);
            }
        }
        __syncthreads();
        __half* Vt = (__half*)out0;
        const int b = m0 >> 11, s0 = m0 & 2047;
#pragma unroll
        for (int rep = 0; rep < 8; rep++) {
            int i = t + rep * 256;
            int nr = i >> 4, c = (i & 15) * 8;
            int h = (n0 + nr) >> 6, d = (n0 + nr) & 63;
            *(uint4*)(Vt + ((size_t)((b * NH + h) * HD + d)) * SS + s0 + c) =
                *(const uint4*)(T + nr * TP + c);
        }
        return;
    }

#pragma unroll
    for (int mt = 0; mt < 2; mt++) {
        const int mA = m0 + wm * 32 + mt * 16 + g;
        const int mB = mA + 8;
#pragma unroll
        for (int nt = 0; nt < 8; nt++) {
            const int n = n0 + wn * 64 + nt * 8 + 2 * tq;
            const float b0 = bias[n], b1 = bias[n + 1];
            float v0 = acc[mt][nt][0] + b0, v1 = acc[mt][nt][1] + b1;
            float v2 = acc[mt][nt][2] + b0, v3 = acc[mt][nt][3] + b1;
            if (MODE == 0) {
                __half* Xh = (__half*)out0; __half* Xl = (__half*)out1;
                const int h = n >> 6, d = n & 63;
                {
                    int b = mA >> 11, s = mA & 2047;
                    size_t o = ((size_t)((b * NH + h) * SS + s)) * HD + d;
                    uint32_t hi, lo; split2(v0, v1, hi, lo);
                    *(uint32_t*)(Xh + o) = hi; *(uint32_t*)(Xl + o) = lo;
                }
                {
                    int b = mB >> 11, s = mB & 2047;
                    size_t o = ((size_t)((b * NH + h) * SS + s)) * HD + d;
                    uint32_t hi, lo; split2(v2, v3, hi, lo);
                    *(uint32_t*)(Xh + o) = hi; *(uint32_t*)(Xl + o) = lo;
                }
            } else {
                float* O = (float*)out0;
                *(float2*)(O + (size_t)mA * EMB + n) = make_float2(v0, v1);
                *(float2*)(O + (size_t)mB * EMB + n) = make_float2(v2, v3);
            }
        }
    }
}

// Persistent fused Q/K/V projection: work-stealing over 768 tiles.
__global__ __launch_bounds__(256, 2) void proj_fused(
    const float* __restrict__ bq, const float* __restrict__ bk,
    const float* __restrict__ bv)
{
    extern __shared__ char sm[];
    __shared__ int s_tile;
    for (;;) {
        __syncthreads();                 // smem/reg reuse fence between tiles
        if (threadIdx.x == 0) s_tile = atomicAdd(&g_ctrP, 1);
        __syncthreads();
        const int tile = s_tile;
        if (tile >= P_TILES) break;
        const int z  = tile % 3;         // interleave heavy(Q,K)/light(V) jobs
        const int r  = tile / 3;
        const int bx = r & 31, by = r >> 5;
        if (z == 0)
            gemm_body<0, 3>(sm, g_iqh, g_iql, g_wqh, g_wql, bq, g_Qh, g_Ql, bx, by);
        else if (z == 1)
            gemm_body<0, 3>(sm, g_ikh, g_ikl, g_wkh, g_wkl, bk, g_Kh, g_Kl, bx, by);
        else
            gemm_body<1, 1>(sm, g_ivh, nullptr, g_wvh, nullptr, bv, g_Vt, nullptr, bx, by);
    }
}

// Output projection: grid (32, 8) — single clean wave, no stealing needed.
__global__ __launch_bounds__(256, 2) void out_proj(
    const float* __restrict__ bo, float* __restrict__ out)
{
    extern __shared__ char sm[];
    gemm_body<2, 1>(sm, g_cth, nullptr, g_woh, nullptr, bo, out, nullptr,
                    blockIdx.x, blockIdx.y);
}

// ---------------------------------------------------------------------------
// Flash attention, fp16 mma, 2 CTAs/SM, persistent work-stealing over 512
// (bh, q-tile) jobs. 128 q-rows/tile, 64-kv chunks, 8 warps.
// QK^T 3-pass; PV single-pass P-hi x V. Softmax in base-2.
// ---------------------------------------------------------------------------
#define FTILE  9216          // 64*144
#define FSTAGE 27648         // Kh, Kl, Vt tiles
#define SCL2   0.18033688011112042f   // 0.125 * log2(e)

__device__ __forceinline__ void flash_load(uint32_t base, int bh, int kv0, int t) {
#pragma unroll
    for (int rep = 0; rep < 2; rep++) {
        int c = t + rep * 256, r = c >> 3, cc = c & 7;
        size_t ko = ((size_t)bh * SS + kv0 + r) * HD + cc * 8;
        cp16(base + r * 144 + cc * 16,             g_Kh + ko);
        cp16(base + FTILE + r * 144 + cc * 16,     g_Kl + ko);
        cp16(base + 2 * FTILE + r * 144 + cc * 16, g_Vt + ((size_t)bh * HD + r) * SS + kv0 + cc * 8);
    }
    CP_COMMIT();
}

__device__ __forceinline__ void flash_tile(char* sm, int bh, int q0)
{
    const uint32_t sb = smem_u32(sm);
    const int t = threadIdx.x, w = t >> 5, l = t & 31;
    const int g = l >> 2, tq = l & 3;

    uint32_t qh[4][4], ql[4][4];
    {
        const __half* Qhp = g_Qh + ((size_t)bh * SS + q0 + w * 16) * HD;
        const __half* Qlp = g_Ql + ((size_t)bh * SS + q0 + w * 16) * HD;
#pragma unroll
        for (int kt = 0; kt < 4; kt++) {
            int k0 = kt * 16 + 2 * tq;
            qh[kt][0] = *(const uint32_t*)(Qhp + (size_t)g * HD + k0);
            qh[kt][1] = *(const uint32_t*)(Qhp + (size_t)(g + 8) * HD + k0);
            qh[kt][2] = *(const uint32_t*)(Qhp + (size_t)g * HD + k0 + 8);
            qh[kt][3] = *(const uint32_t*)(Qhp + (size_t)(g + 8) * HD + k0 + 8);
            ql[kt][0] = *(const uint32_t*)(Qlp + (size_t)g * HD + k0);
            ql[kt][1] = *(const uint32_t*)(Qlp + (size_t)(g + 8) * HD + k0);
            ql[kt][2] = *(const uint32_t*)(Qlp + (size_t)g * HD + k0 + 8);
            ql[kt][3] = *(const uint32_t*)(Qlp + (size_t)(g + 8) * HD + k0 + 8);
        }
    }

    float o[8][4];
#pragma unroll
    for (int nt = 0; nt < 8; nt++)
#pragma unroll
        for (int c = 0; c < 4; c++) o[nt][c] = 0.f;
    float mA = -1e30f, mB = -1e30f, lA = 0.f, lB = 0.f;

    flash_load(sb, bh, 0, t);

    for (int ci = 0; ci < 32; ci++) {
        CP_WAIT0();
        __syncthreads();
        if (ci + 1 < 32)
            flash_load(sb + ((ci + 1) & 1) * FSTAGE, bh, (ci + 1) * 64, t);
        const uint32_t base = sb + (ci & 1) * FSTAGE;

        // ---- S = Q K^T (3-pass) ----
        float s[8][4];
#pragma unroll
        for (int nt = 0; nt < 8; nt++)
#pragma unroll
            for (int c = 0; c < 4; c++) s[nt][c] = 0.f;

#pragma unroll
        for (int kt = 0; kt < 4; kt++) {
#pragma unroll
            for (int p = 0; p < 4; p++) {
                uint32_t off = (uint32_t)((p * 16 + (l & 7) + (((l >> 4) & 1) << 3)) * 144
                                          + (kt * 16 + ((l >> 3) & 1) * 8) * 2);
                uint32_t r[4];
                ldmx4(r, base + off);                  // Kh
                mma_f16(s[2 * p],     qh[kt], r[0], r[1]);
                mma_f16(s[2 * p + 1], qh[kt], r[2], r[3]);
                mma_f16(s[2 * p],     ql[kt], r[0], r[1]);
                mma_f16(s[2 * p + 1], ql[kt], r[2], r[3]);
                ldmx4(r, base + FTILE + off);          // Kl
                mma_f16(s[2 * p],     qh[kt], r[0], r[1]);
                mma_f16(s[2 * p + 1], qh[kt], r[2], r[3]);
            }
        }

        // ---- online softmax (base-2 logits) ----
        float mxA = -1e30f, mxB = -1e30f;
#pragma unroll
        for (int nt = 0; nt < 8; nt++) {
#pragma unroll
            for (int c = 0; c < 4; c++) s[nt][c] *= SCL2;
            mxA = fmaxf(mxA, fmaxf(s[nt][0], s[nt][1]));
            mxB = fmaxf(mxB, fmaxf(s[nt][2], s[nt][3]));
        }
        mxA = fmaxf(mxA, __shfl_xor_sync(0xffffffffu, mxA, 1));
        mxA = fmaxf(mxA, __shfl_xor_sync(0xffffffffu, mxA, 2));
        mxB = fmaxf(mxB, __shfl_xor_sync(0xffffffffu, mxB, 1));
        mxB = fmaxf(mxB, __shfl_xor_sync(0xffffffffu, mxB, 2));
        float nmA = fmaxf(mA, mxA), nmB = fmaxf(mB, mxB);
        float aA = fexp2(mA - nmA), aB = fexp2(mB - nmB);
        mA = nmA; mB = nmB;
        float sA = 0.f, sB = 0.f;
#pragma unroll
        for (int nt = 0; nt < 8; nt++) {
            s[nt][0] = fexp2(s[nt][0] - nmA);
            s[nt][1] = fexp2(s[nt][1] - nmA);
            s[nt][2] = fexp2(s[nt][2] - nmB);
            s[nt][3] = fexp2(s[nt][3] - nmB);
            sA += s[nt][0] + s[nt][1];
            sB += s[nt][2] + s[nt][3];
        }
        sA += __shfl_xor_sync(0xffffffffu, sA, 1);
        sA += __shfl_xor_sync(0xffffffffu, sA, 2);
        sB += __shfl_xor_sync(0xffffffffu, sB, 1);
        sB += __shfl_xor_sync(0xffffffffu, sB, 2);
        lA = lA * aA + sA;
        lB = lB * aB + sB;
#pragma unroll
        for (int nt = 0; nt < 8; nt++) {
            o[nt][0] *= aA; o[nt][1] *= aA;
            o[nt][2] *= aB; o[nt][3] *= aB;
        }

        // ---- O += P V  (single-pass: P-hi x V) ----
#pragma unroll
        for (int kt = 0; kt < 4; kt++) {
            uint32_t ph[4];
            const int j0 = 2 * kt, j1 = 2 * kt + 1;
            ph[0] = h2u(__floats2half2_rn(s[j0][0], s[j0][1]));
            ph[1] = h2u(__floats2half2_rn(s[j0][2], s[j0][3]));
            ph[2] = h2u(__floats2half2_rn(s[j1][0], s[j1][1]));
            ph[3] = h2u(__floats2half2_rn(s[j1][2], s[j1][3]));
#pragma unroll
            for (int p = 0; p < 4; p++) {
                uint32_t off = (uint32_t)((p * 16 + (l & 7) + (((l >> 4) & 1) << 3)) * 144
                                          + (kt * 16 + ((l >> 3) & 1) * 8) * 2);
                uint32_t r[4];
                ldmx4(r, base + 2 * FTILE + off);
                mma_f16(o[2 * p],     ph, r[0], r[1]);
                mma_f16(o[2 * p + 1], ph, r[2], r[3]);
            }
        }
    }

    const float iA = 1.f / lA, iB = 1.f / lB;
    const int b = bh >> 4, h = bh & 15;
    const size_t rowA = (size_t)b * SS + q0 + w * 16 + g;
    const size_t rowB = rowA + 8;
#pragma unroll
    for (int nt = 0; nt < 8; nt++) {
        const int n = h * HD + nt * 8 + 2 * tq;
        *(uint32_t*)(g_cth + rowA * EMB + n) =
            h2u(__floats2half2_rn(o[nt][0] * iA, o[nt][1] * iA));
        *(uint32_t*)(g_cth + rowB * EMB + n) =
            h2u(__floats2half2_rn(o[nt][2] * iB, o[nt][3] * iB));
    }
}

__global__ __launch_bounds__(256, 2) void flash16()
{
    extern __shared__ char sm[];
    __shared__ int s_tile;
    for (;;) {
        __syncthreads();                 // fence smem reuse between tiles
        if (threadIdx.x == 0) s_tile = atomicAdd(&g_ctrF, 1);
        __syncthreads();
        const int tile = s_tile;
        if (tile >= F_TILES) break;
        const int bh = tile >> 4;        // same-bh tiles consecutive (K/V L2 reuse)
        const int q0 = (tile & 15) * 128;
        flash_tile(sm, bh, q0);
    }
}

// ---------------------------------------------------------------------------
extern "C" void kernel_launch(void* const* d_in, const int* in_sizes, int n_in,
                              void* d_out, int out_size)
{
    const float* q  = (const float*)d_in[0];
    const float* k  = (const float*)d_in[1];
    const float* v  = (const float*)d_in[2];
    const float* Wq = (const float*)d_in[3];
    const float* Wk = (const float*)d_in[4];
    const float* Wv = (const float*)d_in[5];
    const float* bq = (const float*)d_in[6];
    const float* bk = (const float*)d_in[7];
    const float* bv = (const float*)d_in[8];
    const float* Wo = (const float*)d_in[9];
    const float* bo = (const float*)d_in[10];
    float* out = (float*)d_out;

    const int GSM = 2 * GSTAGE;    // 81920
    const int FSM = 2 * FSTAGE;    // 55296
    cudaFuncSetAttribute((const void*)proj_fused, cudaFuncAttributeMaxDynamicSharedMemorySize, GSM);
    cudaFuncSetAttribute((const void*)out_proj,   cudaFuncAttributeMaxDynamicSharedMemorySize, GSM);
    cudaFuncSetAttribute((const void*)flash16,    cudaFuncAttributeMaxDynamicSharedMemorySize, FSM);

    int nsm = 148;
    cudaDeviceGetAttribute(&nsm, cudaDevAttrMultiProcessorCount, 0);
    int gp = 2 * nsm; if (gp > P_TILES) gp = P_TILES;
    int gf = 2 * nsm; if (gf > F_TILES) gf = F_TILES;

    prep_split<<<MT * EMB / (256 * 4), 256>>>(q, k, v);
    prep_w<<<dim3(32, 32, 4), dim3(32, 8)>>>(Wq, Wk, Wv, Wo);

    proj_fused<<<gp, 256, GSM>>>(bq, bk, bv);

    flash16<<<gf, 256, FSM>>>();

    out_proj<<<dim3(MT / 128, EMB / 128), 256, GSM>>>(bo, out);
}

// round 17
// speedup vs baseline: 1.1053x; 1.1053x over previous
#include <cuda_runtime.h>
#include <cuda_fp16.h>
#include <cstdint>

#define EMB 1024
#define NH  16
#define HD  64
#define BB  2
#define SS  2048
#define MT  4096

#define SCL2 0.18033688011112042f   // 0.125 * log2(e), folded into Q projection

// ---------------------------------------------------------------------------
// Device global scratch (allocation-free rule)
// ---------------------------------------------------------------------------
__device__ __half g_iqh[MT*EMB], g_iql[MT*EMB];
__device__ __half g_ikh[MT*EMB], g_ikl[MT*EMB];
__device__ __half g_ivh[MT*EMB];
__device__ __half g_wqh[EMB*EMB], g_wql[EMB*EMB];
__device__ __half g_wkh[EMB*EMB], g_wkl[EMB*EMB];
__device__ __half g_wvh[EMB*EMB];
__device__ __half g_woh[EMB*EMB];
__device__ __half g_Qh[MT*EMB], g_Ql[MT*EMB];     // [B,H,S,D], pre-scaled by SCL2
__device__ __half g_Kh[MT*EMB], g_Kl[MT*EMB];     // [B,H,S,D]
__device__ __half g_Vt[MT*EMB];                   // [B,H,D,S]
__device__ __half g_cth[MT*EMB];                  // [M,E] (hi only)

// ---------------------------------------------------------------------------
// PTX helpers
// ---------------------------------------------------------------------------
__device__ __forceinline__ uint32_t smem_u32(const void* p) {
    uint32_t a;
    asm("{ .reg .u64 t; cvta.to.shared.u64 t, %1; cvt.u32.u64 %0, t; }" : "=r"(a) : "l"(p));
    return a;
}
__device__ __forceinline__ void cp16(uint32_t dst, const void* src) {
    asm volatile("cp.async.cg.shared.global [%0], [%1], 16;" :: "r"(dst), "l"(src));
}
#define CP_COMMIT() asm volatile("cp.async.commit_group;" ::: "memory")
#define CP_WAIT0()  asm volatile("cp.async.wait_group 0;" ::: "memory")

__device__ __forceinline__ void ldmx4(uint32_t* r, uint32_t a) {
    asm volatile("ldmatrix.sync.aligned.m8n8.x4.shared.b16 {%0,%1,%2,%3}, [%4];"
                 : "=r"(r[0]), "=r"(r[1]), "=r"(r[2]), "=r"(r[3]) : "r"(a));
}
__device__ __forceinline__ void mma_f16(float* d, const uint32_t* a, uint32_t b0, uint32_t b1) {
    asm volatile(
        "mma.sync.aligned.m16n8k16.row.col.f32.f16.f16.f32 "
        "{%0,%1,%2,%3},{%4,%5,%6,%7},{%8,%9},{%0,%1,%2,%3};"
        : "+f"(d[0]), "+f"(d[1]), "+f"(d[2]), "+f"(d[3])
        : "r"(a[0]), "r"(a[1]), "r"(a[2]), "r"(a[3]), "r"(b0), "r"(b1));
}
__device__ __forceinline__ float fexp2(float x) {
    float y;
    asm("ex2.approx.f32 %0, %1;" : "=f"(y) : "f"(x));
    return y;
}
__device__ __forceinline__ uint32_t h2u(__half2 h) { return *reinterpret_cast<uint32_t*>(&h); }
__device__ __forceinline__ void split2(float x, float y, uint32_t& hi, uint32_t& lo) {
    __half hx = __float2half_rn(x), hy = __float2half_rn(y);
    hi = h2u(__halves2half2(hx, hy));
    __half lx = __float2half_rn(x - __half2float(hx));
    __half ly = __float2half_rn(y - __half2float(hy));
    lo = h2u(__halves2half2(lx, ly));
}

// ---------------------------------------------------------------------------
// Fused prep: blocks [0,4096) split q,k (hi/lo) + round v;
// blocks [4096,8192) transpose weights to [N][K] K-major (+split Wq,Wk).
// ---------------------------------------------------------------------------
__device__ __forceinline__ void split_store4(float4 a, __half* hp, __half* lp, int i4) {
    uint32_t h0, l0, h1, l1;
    split2(a.x, a.y, h0, l0);
    split2(a.z, a.w, h1, l1);
    uint2 uh; uh.x = h0; uh.y = h1;
    uint2 ul; ul.x = l0; ul.y = l1;
    ((uint2*)hp)[i4] = uh;
    ((uint2*)lp)[i4] = ul;
}
__global__ void prep_all(const float* __restrict__ q, const float* __restrict__ k,
                         const float* __restrict__ v,
                         const float* __restrict__ Wq, const float* __restrict__ Wk,
                         const float* __restrict__ Wv, const float* __restrict__ Wo)
{
    const int b = blockIdx.x;
    const int t = threadIdx.x;
    if (b < 4096) {
        int i4 = b * 256 + t;
        split_store4(((const float4*)q)[i4], g_iqh, g_iql, i4);
        split_store4(((const float4*)k)[i4], g_ikh, g_ikl, i4);
        float4 a = ((const float4*)v)[i4];
        uint2 uh;
        uh.x = h2u(__floats2half2_rn(a.x, a.y));
        uh.y = h2u(__floats2half2_rn(a.z, a.w));
        ((uint2*)g_ivh)[i4] = uh;
        return;
    }
    __shared__ float tile[32][33];
    const int wb = b - 4096;
    const int z  = wb >> 10;
    const int r0 = wb & 1023;
    const int k0 = (r0 & 31) * 32, n0 = (r0 >> 5) * 32;
    const int tx = t & 31, ty = t >> 5;
    const float* src = (z == 0) ? Wq : (z == 1) ? Wk : (z == 2) ? Wv : Wo;

    for (int r = ty; r < 32; r += 8) {
        int kk = k0 + r, n = n0 + tx;
        tile[r][tx] = (z < 3) ? src[((size_t)(n >> 6) * EMB + kk) * HD + (n & 63)]
                              : src[(size_t)kk * EMB + n];
    }
    __syncthreads();
    for (int r = ty; r < 32; r += 8) {
        int n = n0 + r, kk = k0 + tx;
        float vv = tile[tx][r];
        size_t o = (size_t)n * EMB + kk;
        __half h = __float2half_rn(vv);
        if (z == 0) {
            g_wqh[o] = h;
            g_wql[o] = __float2half_rn(vv - __half2float(h));
        } else if (z == 1) {
            g_wkh[o] = h;
            g_wkl[o] = __float2half_rn(vv - __half2float(h));
        } else if (z == 2) {
            g_wvh[o] = h;
        } else {
            g_woh[o] = h;
        }
    }
}

// ---------------------------------------------------------------------------
// fp16 GEMM body, CTA 128x128, BK=32, 8 warps (4m x 2n), 2 CTAs/SM.
// Single-barrier software pipeline: [wait0; sync; issue next; compute].
// PASSES=3: AhBh+AhBl+AlBh.  PASSES=1: AhBh only.
// MODE 0: scatter hi/lo [B,H,S,D].  MODE 3: same but scaled by SCL2 (Q).
// MODE 1: smem-transposed fp16 [B,H,D,S].  MODE 2: fp32 linear [M,1024].
// ---------------------------------------------------------------------------
#define GSTAGE 40960   // Ah(10240) + Al + Bh + Bl slots

template<int PASSES>
__device__ __forceinline__ void gemm_load(uint32_t base,
    const __half* Ah, const __half* Al, const __half* Bh, const __half* Bl,
    int m0, int n0, int k0, int t)
{
#pragma unroll
    for (int rep = 0; rep < 2; rep++) {
        int c = t + rep * 256, r = c >> 2, cc = c & 3;
        size_t ao = (size_t)(m0 + r) * EMB + k0 + cc * 8;
        size_t bo = (size_t)(n0 + r) * EMB + k0 + cc * 8;
        uint32_t d = base + r * 80 + cc * 16;
        cp16(d, Ah + ao);
        if (PASSES == 3) cp16(d + 10240, Al + ao);
        cp16(d + 20480, Bh + bo);
        if (PASSES == 3) cp16(d + 30720, Bl + bo);
    }
    CP_COMMIT();
}

template<int MODE, int PASSES>
__device__ __forceinline__ void gemm_body(char* sm,
    const __half* Ah, const __half* Al,
    const __half* Bh, const __half* Bl,
    const float* bias, void* out0, void* out1, int bx, int by)
{
    const uint32_t sb = smem_u32(sm);
    const int t = threadIdx.x, wid = t >> 5, l = t & 31;
    const int g = l >> 2, tq = l & 3;
    const int m0 = bx * 128, n0 = by * 128;
    const int wm = wid & 3, wn = wid >> 2;

    float acc[2][8][4];
#pragma unroll
    for (int mt = 0; mt < 2; mt++)
#pragma unroll
        for (int nt = 0; nt < 8; nt++)
#pragma unroll
            for (int c = 0; c < 4; c++) acc[mt][nt][c] = 0.f;

    gemm_load<PASSES>(sb, Ah, Al, Bh, Bl, m0, n0, 0, t);

    for (int i = 0; i < 32; i++) {
        CP_WAIT0();
        __syncthreads();                 // publishes stage i; fences reads of slot (i+1)&1
        if (i + 1 < 32)
            gemm_load<PASSES>(sb + ((i + 1) & 1) * GSTAGE, Ah, Al, Bh, Bl, m0, n0, (i + 1) * 32, t);
        const uint32_t base = sb + (i & 1) * GSTAGE;

#pragma unroll
        for (int kt = 0; kt < 2; kt++) {
            uint32_t afh[2][4], afl[2][4];
#pragma unroll
            for (int mt = 0; mt < 2; mt++) {
                uint32_t off = (uint32_t)((wm * 32 + mt * 16 + (l & 15)) * 80
                                          + (kt * 16 + ((l >> 4) << 3)) * 2);
                ldmx4(afh[mt], base + off);
                if (PASSES == 3) ldmx4(afl[mt], base + 10240 + off);
            }
#pragma unroll
            for (int p = 0; p < 4; p++) {
                uint32_t off = (uint32_t)((wn * 64 + p * 16 + (l & 7) + (((l >> 4) & 1) << 3)) * 80
                                          + (kt * 16 + ((l >> 3) & 1) * 8) * 2);
                uint32_t rb[4];
                ldmx4(rb, base + 20480 + off);          // Bh frag
#pragma unroll
                for (int mt = 0; mt < 2; mt++) {
                    mma_f16(acc[mt][2 * p],     afh[mt], rb[0], rb[1]);
                    mma_f16(acc[mt][2 * p + 1], afh[mt], rb[2], rb[3]);
                    if (PASSES == 3) {
                        mma_f16(acc[mt][2 * p],     afl[mt], rb[0], rb[1]);
                        mma_f16(acc[mt][2 * p + 1], afl[mt], rb[2], rb[3]);
                    }
                }
                if (PASSES == 3) {
                    ldmx4(rb, base + 30720 + off);      // Bl frag
#pragma unroll
                    for (int mt = 0; mt < 2; mt++) {
                        mma_f16(acc[mt][2 * p],     afh[mt], rb[0], rb[1]);
                        mma_f16(acc[mt][2 * p + 1], afh[mt], rb[2], rb[3]);
                    }
                }
            }
        }
    }
    __syncthreads();                     // all compute done before any smem reuse

    if (MODE == 1) {
        // smem-staged transpose: T[128 n][136 pad] halves, then coalesced
        // 16B stores along S into g_Vt [B,H,D,S].
        __half* T = (__half*)sm;
        const int TP = 136;
#pragma unroll
        for (int mt = 0; mt < 2; mt++) {
            const int mlocA = wm * 32 + mt * 16 + g;
            const int mlocB = mlocA + 8;
#pragma unroll
            for (int nt = 0; nt < 8; nt++) {
                const int nloc = wn * 64 + nt * 8 + 2 * tq;
                const int n = n0 + nloc;
                const float b0 = bias[n], b1 = bias[n + 1];
                T[nloc * TP + mlocA]       = __float2half_rn(acc[mt][nt][0] + b0);
                T[(nloc + 1) * TP + mlocA] = __float2half_rn(acc[mt][nt][1] + b1);
                T[nloc * TP + mlocB]       = __float2half_rn(acc[mt][nt][2] + b0);
                T[(nloc + 1) * TP + mlocB] = __float2half_rn(acc[mt][nt][3] + b1);
            }
        }
        __syncthreads();
        __half* Vt = (__half*)out0;
        const int b = m0 >> 11, s0 = m0 & 2047;
#pragma unroll
        for (int rep = 0; rep < 8; rep++) {
            int i = t + rep * 256;
            int nr = i >> 4, c = (i & 15) * 8;
            int h = (n0 + nr) >> 6, d = (n0 + nr) & 63;
            *(uint4*)(Vt + ((size_t)((b * NH + h) * HD + d)) * SS + s0 + c) =
                *(const uint4*)(T + nr * TP + c);
        }
        return;
    }

#pragma unroll
    for (int mt = 0; mt < 2; mt++) {
        const int mA = m0 + wm * 32 + mt * 16 + g;
        const int mB = mA + 8;
#pragma unroll
        for (int nt = 0; nt < 8; nt++) {
            const int n = n0 + wn * 64 + nt * 8 + 2 * tq;
            const float b0 = bias[n], b1 = bias[n + 1];
            float v0 = acc[mt][nt][0] + b0, v1 = acc[mt][nt][1] + b1;
            float v2 = acc[mt][nt][2] + b0, v3 = acc[mt][nt][3] + b1;
            if (MODE == 3) {
                v0 *= SCL2; v1 *= SCL2; v2 *= SCL2; v3 *= SCL2;
            }
            if (MODE == 0 || MODE == 3) {
                __half* Xh = (__half*)out0; __half* Xl = (__half*)out1;
                const int h = n >> 6, d = n & 63;
                {
                    int b = mA >> 11, s = mA & 2047;
                    size_t o = ((size_t)((b * NH + h) * SS + s)) * HD + d;
                    uint32_t hi, lo; split2(v0, v1, hi, lo);
                    *(uint32_t*)(Xh + o) = hi; *(uint32_t*)(Xl + o) = lo;
                }
                {
                    int b = mB >> 11, s = mB & 2047;
                    size_t o = ((size_t)((b * NH + h) * SS + s)) * HD + d;
                    uint32_t hi, lo; split2(v2, v3, hi, lo);
                    *(uint32_t*)(Xh + o) = hi; *(uint32_t*)(Xl + o) = lo;
                }
            } else {
                float* O = (float*)out0;
                *(float2*)(O + (size_t)mA * EMB + n) = make_float2(v0, v1);
                *(float2*)(O + (size_t)mB * EMB + n) = make_float2(v2, v3);
            }
        }
    }
}

// Fused Q/K/V projection launch: grid (32, 8, 3)
__global__ __launch_bounds__(256, 2) void proj_fused(
    const float* __restrict__ bq, const float* __restrict__ bk,
    const float* __restrict__ bv)
{
    extern __shared__ char sm[];
    const int z = blockIdx.z;
    if (z == 0)
        gemm_body<3, 3>(sm, g_iqh, g_iql, g_wqh, g_wql, bq, g_Qh, g_Ql,
                        blockIdx.x, blockIdx.y);
    else if (z == 1)
        gemm_body<0, 3>(sm, g_ikh, g_ikl, g_wkh, g_wkl, bk, g_Kh, g_Kl,
                        blockIdx.x, blockIdx.y);
    else
        gemm_body<1, 1>(sm, g_ivh, nullptr, g_wvh, nullptr, bv, g_Vt, nullptr,
                        blockIdx.x, blockIdx.y);
}

// Output projection: grid (32, 8)
__global__ __launch_bounds__(256, 2) void out_proj(
    const float* __restrict__ bo, float* __restrict__ out)
{
    extern __shared__ char sm[];
    gemm_body<2, 1>(sm, g_cth, nullptr, g_woh, nullptr, bo, out, nullptr,
                    blockIdx.x, blockIdx.y);
}

// ---------------------------------------------------------------------------
// Flash attention, fp16 mma, 2 CTAs/SM. 128 q-rows/CTA, 64-kv chunks, 8 warps.
// QK^T 3-pass (Q pre-scaled by SCL2 => logits already base-2); PV single-pass.
// ---------------------------------------------------------------------------
#define FTILE  9216          // 64*144
#define FSTAGE 27648         // Kh, Kl, Vt tiles

__device__ __forceinline__ void flash_load(uint32_t base, int bh, int kv0, int t) {
#pragma unroll
    for (int rep = 0; rep < 2; rep++) {
        int c = t + rep * 256, r = c >> 3, cc = c & 7;
        size_t ko = ((size_t)bh * SS + kv0 + r) * HD + cc * 8;
        cp16(base + r * 144 + cc * 16,             g_Kh + ko);
        cp16(base + FTILE + r * 144 + cc * 16,     g_Kl + ko);
        cp16(base + 2 * FTILE + r * 144 + cc * 16, g_Vt + ((size_t)bh * HD + r) * SS + kv0 + cc * 8);
    }
    CP_COMMIT();
}

__global__ __launch_bounds__(256, 2) void flash16()
{
    extern __shared__ char sm[];
    const uint32_t sb = smem_u32(sm);
    const int t = threadIdx.x, w = t >> 5, l = t & 31;
    const int g = l >> 2, tq = l & 3;
    const int bh = blockIdx.y, q0 = blockIdx.x * 128;

    uint32_t qh[4][4], ql[4][4];
    {
        const __half* Qhp = g_Qh + ((size_t)bh * SS + q0 + w * 16) * HD;
        const __half* Qlp = g_Ql + ((size_t)bh * SS + q0 + w * 16) * HD;
#pragma unroll
        for (int kt = 0; kt < 4; kt++) {
            int k0 = kt * 16 + 2 * tq;
            qh[kt][0] = *(const uint32_t*)(Qhp + (size_t)g * HD + k0);
            qh[kt][1] = *(const uint32_t*)(Qhp + (size_t)(g + 8) * HD + k0);
            qh[kt][2] = *(const uint32_t*)(Qhp + (size_t)g * HD + k0 + 8);
            qh[kt][3] = *(const uint32_t*)(Qhp + (size_t)(g + 8) * HD + k0 + 8);
            ql[kt][0] = *(const uint32_t*)(Qlp + (size_t)g * HD + k0);
            ql[kt][1] = *(const uint32_t*)(Qlp + (size_t)(g + 8) * HD + k0);
            ql[kt][2] = *(const uint32_t*)(Qlp + (size_t)g * HD + k0 + 8);
            ql[kt][3] = *(const uint32_t*)(Qlp + (size_t)(g + 8) * HD + k0 + 8);
        }
    }

    float o[8][4];
#pragma unroll
    for (int nt = 0; nt < 8; nt++)
#pragma unroll
        for (int c = 0; c < 4; c++) o[nt][c] = 0.f;
    float mA = -1e30f, mB = -1e30f, lA = 0.f, lB = 0.f;

    flash_load(sb, bh, 0, t);

    for (int ci = 0; ci < 32; ci++) {
        CP_WAIT0();
        __syncthreads();
        if (ci + 1 < 32)
            flash_load(sb + ((ci + 1) & 1) * FSTAGE, bh, (ci + 1) * 64, t);
        const uint32_t base = sb + (ci & 1) * FSTAGE;

        // ---- S = Q K^T (3-pass; logits already base-2 scaled) ----
        float s[8][4];
#pragma unroll
        for (int nt = 0; nt < 8; nt++)
#pragma unroll
            for (int c = 0; c < 4; c++) s[nt][c] = 0.f;

#pragma unroll
        for (int kt = 0; kt < 4; kt++) {
#pragma unroll
            for (int p = 0; p < 4; p++) {
                uint32_t off = (uint32_t)((p * 16 + (l & 7) + (((l >> 4) & 1) << 3)) * 144
                                          + (kt * 16 + ((l >> 3) & 1) * 8) * 2);
                uint32_t r[4];
                ldmx4(r, base + off);                  // Kh
                mma_f16(s[2 * p],     qh[kt], r[0], r[1]);
                mma_f16(s[2 * p + 1], qh[kt], r[2], r[3]);
                mma_f16(s[2 * p],     ql[kt], r[0], r[1]);
                mma_f16(s[2 * p + 1], ql[kt], r[2], r[3]);
                ldmx4(r, base + FTILE + off);          // Kl
                mma_f16(s[2 * p],     qh[kt], r[0], r[1]);
                mma_f16(s[2 * p + 1], qh[kt], r[2], r[3]);
            }
        }

        // ---- online softmax (base-2 logits) ----
        float mxA = -1e30f, mxB = -1e30f;
#pragma unroll
        for (int nt = 0; nt < 8; nt++) {
            mxA = fmaxf(mxA, fmaxf(s[nt][0], s[nt][1]));
            mxB = fmaxf(mxB, fmaxf(s[nt][2], s[nt][3]));
        }
        mxA = fmaxf(mxA, __shfl_xor_sync(0xffffffffu, mxA, 1));
        mxA = fmaxf(mxA, __shfl_xor_sync(0xffffffffu, mxA, 2));
        mxB = fmaxf(mxB, __shfl_xor_sync(0xffffffffu, mxB, 1));
        mxB = fmaxf(mxB, __shfl_xor_sync(0xffffffffu, mxB, 2));
        float nmA = fmaxf(mA, mxA), nmB = fmaxf(mB, mxB);
        float aA = fexp2(mA - nmA), aB = fexp2(mB - nmB);
        mA = nmA; mB = nmB;
        float sA = 0.f, sB = 0.f;
#pragma unroll
        for (int nt = 0; nt < 8; nt++) {
            s[nt][0] = fexp2(s[nt][0] - nmA);
            s[nt][1] = fexp2(s[nt][1] - nmA);
            s[nt][2] = fexp2(s[nt][2] - nmB);
            s[nt][3] = fexp2(s[nt][3] - nmB);
            sA += s[nt][0] + s[nt][1];
            sB += s[nt][2] + s[nt][3];
        }
        sA += __shfl_xor_sync(0xffffffffu, sA, 1);
        sA += __shfl_xor_sync(0xffffffffu, sA, 2);
        sB += __shfl_xor_sync(0xffffffffu, sB, 1);
        sB += __shfl_xor_sync(0xffffffffu, sB, 2);
        lA = lA * aA + sA;
        lB = lB * aB + sB;
#pragma unroll
        for (int nt = 0; nt < 8; nt++) {
            o[nt][0] *= aA; o[nt][1] *= aA;
            o[nt][2] *= aB; o[nt][3] *= aB;
        }

        // ---- O += P V  (single-pass: P-hi x V) ----
#pragma unroll
        for (int kt = 0; kt < 4; kt++) {
            uint32_t ph[4];
            const int j0 = 2 * kt, j1 = 2 * kt + 1;
            ph[0] = h2u(__floats2half2_rn(s[j0][0], s[j0][1]));
            ph[1] = h2u(__floats2half2_rn(s[j0][2], s[j0][3]));
            ph[2] = h2u(__floats2half2_rn(s[j1][0], s[j1][1]));
            ph[3] = h2u(__floats2half2_rn(s[j1][2], s[j1][3]));
#pragma unroll
            for (int p = 0; p < 4; p++) {
                uint32_t off = (uint32_t)((p * 16 + (l & 7) + (((l >> 4) & 1) << 3)) * 144
                                          + (kt * 16 + ((l >> 3) & 1) * 8) * 2);
                uint32_t r[4];
                ldmx4(r, base + 2 * FTILE + off);
                mma_f16(o[2 * p],     ph, r[0], r[1]);
                mma_f16(o[2 * p + 1], ph, r[2], r[3]);
            }
        }
    }

    const float iA = 1.f / lA, iB = 1.f / lB;
    const int b = bh >> 4, h = bh & 15;
    const size_t rowA = (size_t)b * SS + q0 + w * 16 + g;
    const size_t rowB = rowA + 8;
#pragma unroll
    for (int nt = 0; nt < 8; nt++) {
        const int n = h * HD + nt * 8 + 2 * tq;
        *(uint32_t*)(g_cth + rowA * EMB + n) =
            h2u(__floats2half2_rn(o[nt][0] * iA, o[nt][1] * iA));
        *(uint32_t*)(g_cth + rowB * EMB + n) =
            h2u(__floats2half2_rn(o[nt][2] * iB, o[nt][3] * iB));
    }
}

// ---------------------------------------------------------------------------
extern "C" void kernel_launch(void* const* d_in, const int* in_sizes, int n_in,
                              void* d_out, int out_size)
{
    const float* q  = (const float*)d_in[0];
    const float* k  = (const float*)d_in[1];
    const float* v  = (const float*)d_in[2];
    const float* Wq = (const float*)d_in[3];
    const float* Wk = (const float*)d_in[4];
    const float* Wv = (const float*)d_in[5];
    const float* bq = (const float*)d_in[6];
    const float* bk = (const float*)d_in[7];
    const float* bv = (const float*)d_in[8];
    const float* Wo = (const float*)d_in[9];
    const float* bo = (const float*)d_in[10];
    float* out = (float*)d_out;

    const int GSM = 2 * GSTAGE;    // 81920
    const int FSM = 2 * FSTAGE;    // 55296
    cudaFuncSetAttribute((const void*)proj_fused, cudaFuncAttributeMaxDynamicSharedMemorySize, GSM);
    cudaFuncSetAttribute((const void*)out_proj,   cudaFuncAttributeMaxDynamicSharedMemorySize, GSM);
    cudaFuncSetAttribute((const void*)flash16,    cudaFuncAttributeMaxDynamicSharedMemorySize, FSM);

    prep_all<<<8192, 256>>>(q, k, v, Wq, Wk, Wv, Wo);

    proj_fused<<<dim3(MT / 128, EMB / 128, 3), 256, GSM>>>(bq, bk, bv);

    flash16<<<dim3(SS / 128, BB * NH), 256, FSM>>>();

    out_proj<<<dim3(MT / 128, EMB / 128), 256, GSM>>>(bo, out);
}